// round 2
// baseline (speedup 1.0000x reference)
#include <cuda_runtime.h>
#include <math.h>

#define BATCH 8
#define HEADS 12
#define SEQ   512
#define DMODEL 768
#define DHEAD 64
#define SCALE 0.03608439182435161f   /* 1/sqrt(768) */

#define PROJ_ELEMS (BATCH*HEADS*SEQ*DHEAD)
#define NBLK_ATTN (16*HEADS*BATCH)
#define P_ELEMS ((size_t)BATCH*HEADS*SEQ*SEQ)

__device__ float g_ql[PROJ_ELEMS];
__device__ float g_qr[PROJ_ELEMS];
__device__ float g_q [PROJ_ELEMS];
__device__ float g_kl[PROJ_ELEMS];
__device__ float g_kr[PROJ_ELEMS];
__device__ float g_k [PROJ_ELEMS];
__device__ double g_partial[NBLK_ATTN];

struct ProjParams {
  const float* X[2];
  const float* W[6];
  const float* B[6];
};

// ---------------------------------------------------------------------------
// Projection GEMM: out = X @ W + bias, scattered to [B,H,S,DK] head layout,
// q-side scaled by 1/sqrt(D). 128x128 tile, K-step 8, 256 threads, 8x8 micro.
// grid = (32, 18, 2); z = query/key side; y selects weight (y/6) and n-tile.
// ---------------------------------------------------------------------------
__global__ __launch_bounds__(256)
void proj_gemm(ProjParams pp) {
  const int side = blockIdx.z;
  const int bn = blockIdx.y;
  const int widx = side*3 + bn/6;
  const float* __restrict__ X  = pp.X[side];
  const float* __restrict__ W  = pp.W[widx];
  const float* __restrict__ Bv = pp.B[widx];
  const int n0 = (bn % 6) * 128;
  const int m0 = blockIdx.x * 128;
  const float scale = (side == 0) ? SCALE : 1.0f;

  float* outp;
  switch (widx) {
    case 0: outp = g_ql; break;
    case 1: outp = g_qr; break;
    case 2: outp = g_q;  break;
    case 3: outp = g_kl; break;
    case 4: outp = g_kr; break;
    default: outp = g_k; break;
  }

  __shared__ float As[8][128];   // transposed A tile [k][m]
  __shared__ float Bs[8][128];   // B tile [k][n]

  const int tid = threadIdx.x;
  const int tx = tid & 15;       // n-group
  const int ty = tid >> 4;       // m-group

  float acc[8][8];
#pragma unroll
  for (int i=0;i<8;i++)
#pragma unroll
    for (int j=0;j<8;j++) acc[i][j]=0.f;

  for (int k0 = 0; k0 < DMODEL; k0 += 8) {
    {
      int row = tid >> 1, seg = tid & 1;
      float4 a = *(const float4*)(X + (size_t)(m0+row)*DMODEL + k0 + seg*4);
      As[seg*4+0][row]=a.x; As[seg*4+1][row]=a.y;
      As[seg*4+2][row]=a.z; As[seg*4+3][row]=a.w;
      int brow = tid >> 5, c4 = tid & 31;
      float4 bvec = *(const float4*)(W + (size_t)(k0+brow)*DMODEL + n0 + c4*4);
      *(float4*)&Bs[brow][c4*4] = bvec;
    }
    __syncthreads();
#pragma unroll
    for (int k = 0; k < 8; k++) {
      float a[8], bfr[8];
      *(float4*)&a[0] = *(const float4*)&As[k][ty*8];
      *(float4*)&a[4] = *(const float4*)&As[k][ty*8+4];
#pragma unroll
      for (int j=0;j<8;j++) bfr[j] = Bs[k][tx + 16*j];
#pragma unroll
      for (int i=0;i<8;i++)
#pragma unroll
        for (int j=0;j<8;j++) acc[i][j] = fmaf(a[i], bfr[j], acc[i][j]);
    }
    __syncthreads();
  }

#pragma unroll
  for (int j=0;j<8;j++) {
    const int nW = n0 + tx + 16*j;
    const float bj = Bv[nW];
    const int hh = nW >> 6;
    const int dk = nW & 63;
#pragma unroll
    for (int i=0;i<8;i++) {
      const int m = m0 + ty*8 + i;
      const int bb = m >> 9;
      const int s  = m & 511;
      outp[(((size_t)bb*HEADS + hh)*SEQ + s)*DHEAD + dk] = (acc[i][j] + bj)*scale;
    }
  }
}

// ---------------------------------------------------------------------------
// Warp utilities
// ---------------------------------------------------------------------------
__device__ __forceinline__ float warpMax(float x) {
#pragma unroll
  for (int off=16; off>0; off>>=1) x = fmaxf(x, __shfl_xor_sync(0xffffffffu, x, off));
  return x;
}
__device__ __forceinline__ float warpSum(float x) {
#pragma unroll
  for (int off=16; off>0; off>>=1) x += __shfl_xor_sync(0xffffffffu, x, off);
  return x;
}
__device__ __forceinline__ float prefixIncl(float x, int lane) {
#pragma unroll
  for (int off=1; off<32; off<<=1) {
    float t = __shfl_up_sync(0xffffffffu, x, off);
    if (lane >= off) x += t;
  }
  return x;
}
__device__ __forceinline__ float suffixIncl(float x, int lane) {
#pragma unroll
  for (int off=1; off<32; off<<=1) {
    float t = __shfl_down_sync(0xffffffffu, x, off);
    if (lane + off < 32) x += t;
  }
  return x;
}

// ---------------------------------------------------------------------------
// Fused attention: one block per (b, h, 32-row q-tile); 256 threads, each
// warp owns 4 q-rows for every row-wise phase.
// ---------------------------------------------------------------------------
__global__ __launch_bounds__(256, 1)
void attn_kernel(const float* __restrict__ mask,
                 const float* __restrict__ span,
                 float* __restrict__ out) {
  extern __shared__ float smbuf[];
  float* Qs = smbuf;                  // [3][32][64]
  float* SL = Qs + 3*32*DHEAD;        // [32][512]
  float* SR = SL + 32*SEQ;            // [32][512]
  float* KT = SR + 32*SEQ;            // [128][68]
  float* RM = KT + 128*68;            // [512]

  __shared__ float wsum[8];

  const int tid = threadIdx.x;
  const int lane = tid & 31;
  const int wid = tid >> 5;
  const int q0 = blockIdx.x * 32;
  const int h = blockIdx.y;
  const int b = blockIdx.z;
  const int bh = (b*HEADS + h)*SEQ;

  // ---- load Q rows (3 branches) + row mask ----
#pragma unroll
  for (int it = 0; it < 6; ++it) {
    int idx = it*256 + tid;          // 1536 float4
    int br = idx >> 9;
    int rem = idx & 511;
    int q = rem >> 4;
    int dc = rem & 15;
    const float* src = (br == 0) ? g_ql : ((br == 1) ? g_qr : g_q);
    float4 v = *(const float4*)(src + (size_t)(bh + q0 + q)*DHEAD + dc*4);
    *(float4*)&Qs[(br*32 + q)*DHEAD + dc*4] = v;
  }
  for (int k = tid; k < SEQ; k += 256) {
    float mv = mask[b*SEQ + k];
    RM[k] = (mv == -10000.0f) ? 1e9f : mv;
  }
  __syncthreads();

  // ---- score phase: dest[q][k] = Q(br) . K(tile), via shared K staging ----
  auto scorePhase = [&](const float* __restrict__ Kbuf, float* __restrict__ dest, int br) {
    for (int kt = 0; kt < 4; ++kt) {
      __syncthreads();   // KT safe to overwrite
#pragma unroll
      for (int it = 0; it < 8; ++it) {
        int idx = it*256 + tid;        // 2048 float4
        int kl = idx >> 4;
        int dc = idx & 15;
        float4 v = *(const float4*)(Kbuf + (size_t)(bh + kt*128 + kl)*DHEAD + dc*4);
        *(float4*)&KT[kl*68 + dc*4] = v;
      }
      __syncthreads();
      float acc[4][4];
#pragma unroll
      for (int i=0;i<4;i++)
#pragma unroll
        for (int j=0;j<4;j++) acc[i][j]=0.f;
#pragma unroll 4
      for (int dc = 0; dc < 16; ++dc) {
        float4 qv[4], kv[4];
#pragma unroll
        for (int i=0;i<4;i++)
          qv[i] = *(const float4*)&Qs[(br*32 + wid*4 + i)*DHEAD + dc*4];
#pragma unroll
        for (int j=0;j<4;j++)
          kv[j] = *(const float4*)&KT[(lane + 32*j)*68 + dc*4];
#pragma unroll
        for (int i=0;i<4;i++)
#pragma unroll
          for (int j=0;j<4;j++) {
            acc[i][j] = fmaf(qv[i].x, kv[j].x, acc[i][j]);
            acc[i][j] = fmaf(qv[i].y, kv[j].y, acc[i][j]);
            acc[i][j] = fmaf(qv[i].z, kv[j].z, acc[i][j]);
            acc[i][j] = fmaf(qv[i].w, kv[j].w, acc[i][j]);
          }
      }
#pragma unroll
      for (int i=0;i<4;i++)
#pragma unroll
        for (int j=0;j<4;j++)
          dest[(wid*4+i)*SEQ + kt*128 + lane + 32*j] = acc[i][j];
    }
  };

  // ================= branch L: theta_l -> inclusive prefix cumsum =========
  scorePhase(g_kl, SL, 0);
  for (int r = 0; r < 4; ++r) {
    const int q = wid*4 + r;
    const int qg = q0 + q;
    float v[16];
    float mx = -1e30f;
#pragma unroll
    for (int jj=0;jj<16;jj++) {
      int k = lane + 32*jj;
      float x = SL[q*SEQ + k];
      v[jj] = (k <= qg) ? x : -1e30f;     // valid: k <= q
      mx = fmaxf(mx, v[jj]);
    }
    mx = warpMax(mx);
    float ssum = 0.f;
#pragma unroll
    for (int jj=0;jj<16;jj++) {
      int k = lane + 32*jj;
      v[jj] = (k <= qg) ? __expf(v[jj]-mx) : 0.f;
      ssum += v[jj];
    }
    ssum = warpSum(ssum);
    float inv = 1.0f/ssum;
    float carry = 0.f;
#pragma unroll
    for (int jj=0;jj<16;jj++) {
      float sc = prefixIncl(v[jj]*inv, lane) + carry;
      SL[q*SEQ + lane + 32*jj] = sc;
      carry = __shfl_sync(0xffffffffu, sc, 31);
    }
  }

  // ===== branch R: theta_r -> inclusive suffix cumsum; SL *= SR ===========
  scorePhase(g_kr, SR, 1);
  for (int r = 0; r < 4; ++r) {
    const int q = wid*4 + r;
    const int qg = q0 + q;
    float v[16];
    float mx = -1e30f;
#pragma unroll
    for (int jj=0;jj<16;jj++) {
      int k = lane + 32*jj;
      float x = SR[q*SEQ + k];
      v[jj] = (k >= qg) ? x : -1e30f;     // valid: k >= q
      mx = fmaxf(mx, v[jj]);
    }
    mx = warpMax(mx);
    float ssum = 0.f;
#pragma unroll
    for (int jj=0;jj<16;jj++) {
      int k = lane + 32*jj;
      v[jj] = (k >= qg) ? __expf(v[jj]-mx) : 0.f;
      ssum += v[jj];
    }
    ssum = warpSum(ssum);
    float inv = 1.0f/ssum;
    float carry = 0.f;
#pragma unroll
    for (int jj=15;jj>=0;jj--) {
      float sc = suffixIncl(v[jj]*inv, lane) + carry;
      int k = lane + 32*jj;
      SL[q*SEQ + k] *= sc;                // SL now holds soft_Mask
      carry = __shfl_sync(0xffffffffu, sc, 0);
    }
  }

  // ===== main branch: p = softmax((scores - rm_q - rm_k) * soft_Mask) =====
  scorePhase(g_k, SR, 2);
  float bce_acc = 0.f;
  for (int r = 0; r < 4; ++r) {
    const int q = wid*4 + r;
    const int qg = q0 + q;
    const float rmq = RM[qg];
    float v[16];
    float mx = -1e30f;
#pragma unroll
    for (int jj=0;jj<16;jj++) {
      int k = lane + 32*jj;
      float raw = SR[q*SEQ + k];
      float m = SL[q*SEQ + k];
      float val = (raw - rmq - RM[k]) * m;
      v[jj] = val;
      mx = fmaxf(mx, val);
    }
    mx = warpMax(mx);
    float ssum = 0.f;
#pragma unroll
    for (int jj=0;jj<16;jj++) {
      v[jj] = __expf(v[jj]-mx);
      ssum += v[jj];
    }
    ssum = warpSum(ssum);
    float inv = 1.0f/ssum;
    const size_t orow = ((size_t)(b*HEADS + h)*SEQ + qg)*SEQ;
    const size_t srow = ((size_t)(h*BATCH + b)*SEQ + qg)*SEQ;
#pragma unroll
    for (int jj=0;jj<16;jj++) {
      int k = lane + 32*jj;
      float p = v[jj]*inv;
      out[orow + k] = p;
      float sp = span[srow + k];
      // BCE identity: -(s*log(sig(p)) + (1-s)*log1p(-sig(p))) = log1p(exp(p)) - s*p
      bce_acc += log1pf(__expf(p)) - sp*p;
    }
  }

  // ---- block reduce BCE partial -> g_partial ----
  bce_acc = warpSum(bce_acc);
  if (lane == 0) wsum[wid] = bce_acc;
  __syncthreads();
  if (tid == 0) {
    double s = 0.0;
#pragma unroll
    for (int w=0;w<8;w++) s += (double)wsum[w];
    g_partial[(blockIdx.z*HEADS + blockIdx.y)*16 + blockIdx.x] = s;
  }
}

// ---------------------------------------------------------------------------
// Final loss reduction
// ---------------------------------------------------------------------------
__global__ void loss_reduce(float* __restrict__ out, int out_size) {
  __shared__ double red[256];
  int tid = threadIdx.x;
  double s = 0.0;
  for (int i = tid; i < NBLK_ATTN; i += 256) s += g_partial[i];
  red[tid] = s;
  __syncthreads();
  for (int off = 128; off > 0; off >>= 1) {
    if (tid < off) red[tid] += red[tid + off];
    __syncthreads();
  }
  if (tid == 0) out[out_size - 1] = (float)(red[0] / (double)P_ELEMS);
}

// ---------------------------------------------------------------------------
extern "C" void kernel_launch(void* const* d_in, const int* in_sizes, int n_in,
                              void* d_out, int out_size) {
  const float* query = (const float*)d_in[0];
  const float* key_t = (const float*)d_in[1];
  const float* mask  = (const float*)d_in[2];
  const float* span  = (const float*)d_in[3];

  ProjParams pp;
  pp.X[0] = query; pp.X[1] = key_t;
  // order: Wql, Wqr, Wq, Wkl, Wkr, Wk  (inputs: Wql,bql,Wkl,bkl,Wqr,bqr,Wkr,bkr,Wq,bq,Wk,bk)
  pp.W[0] = (const float*)d_in[4];  pp.B[0] = (const float*)d_in[5];   // Wql
  pp.W[1] = (const float*)d_in[8];  pp.B[1] = (const float*)d_in[9];   // Wqr
  pp.W[2] = (const float*)d_in[12]; pp.B[2] = (const float*)d_in[13];  // Wq
  pp.W[3] = (const float*)d_in[6];  pp.B[3] = (const float*)d_in[7];   // Wkl
  pp.W[4] = (const float*)d_in[10]; pp.B[4] = (const float*)d_in[11];  // Wkr
  pp.W[5] = (const float*)d_in[14]; pp.B[5] = (const float*)d_in[15];  // Wk

  float* out = (float*)d_out;

  dim3 pgrid(DMODEL*BATCH*SEQ/(128*768/128)/32/6/2*0 + 32, 18, 2);  // (32,18,2)
  proj_gemm<<<pgrid, 256>>>(pp);

  const size_t smem = (size_t)(3*32*DHEAD + 32*SEQ + 32*SEQ + 128*68 + SEQ) * sizeof(float);
  static int attr_set = 0;
  if (!attr_set) {
    cudaFuncSetAttribute(attn_kernel, cudaFuncAttributeMaxDynamicSharedMemorySize, (int)smem);
    attr_set = 1;
  }
  dim3 agrid(SEQ/32, HEADS, BATCH);
  attn_kernel<<<agrid, 256, smem>>>(mask, span, out);

  loss_reduce<<<1, 256>>>(out, out_size);
}

// round 3
// speedup vs baseline: 2.1781x; 2.1781x over previous
#include <cuda_runtime.h>
#include <math.h>

#define BATCH 8
#define HEADS 12
#define SEQ   512
#define DMODEL 768
#define DHEAD 64
#define SCALE 0.03608439182435161f   /* 1/sqrt(768) */

#define PROJ_ELEMS (BATCH*HEADS*SEQ*DHEAD)
#define NBLK_ATTN (16*HEADS*BATCH)
#define P_ELEMS ((size_t)BATCH*HEADS*SEQ*SEQ)

__device__ float g_ql[PROJ_ELEMS];
__device__ float g_qr[PROJ_ELEMS];
__device__ float g_q [PROJ_ELEMS];
__device__ float g_kl[PROJ_ELEMS];
__device__ float g_kr[PROJ_ELEMS];
__device__ float g_k [PROJ_ELEMS];
__device__ double g_partial[NBLK_ATTN];

struct ProjParams {
  const float* X[2];
  const float* W[6];
  const float* B[6];
};

__device__ __forceinline__ unsigned tf32cvt(float f) {
  unsigned u;
  asm("cvt.rna.tf32.f32 %0, %1;" : "=r"(u) : "f"(f));
  return u;
}

__device__ __forceinline__ void mma_tf32(float* c, const unsigned* a, const unsigned* b) {
  asm volatile(
    "mma.sync.aligned.m16n8k8.row.col.f32.tf32.tf32.f32 "
    "{%0,%1,%2,%3},{%4,%5,%6,%7},{%8,%9},{%0,%1,%2,%3};"
    : "+f"(c[0]), "+f"(c[1]), "+f"(c[2]), "+f"(c[3])
    : "r"(a[0]), "r"(a[1]), "r"(a[2]), "r"(a[3]), "r"(b[0]), "r"(b[1]));
}

// ---------------------------------------------------------------------------
// Projection GEMM on tensor cores (tf32):
//   out = (X @ W + bias) [scaled on q-side], scattered to [B,H,S,DK].
// Block tile 128x128, BK=32, 256 threads, warp tile 64x32 (m16n8k8 tf32).
// grid = (32, 6, 6); z = weight index (0..2 query side, 3..5 key side).
// ---------------------------------------------------------------------------
__global__ __launch_bounds__(256)
void proj_tc(ProjParams pp) {
  const int widx = blockIdx.z;
  const int side = widx / 3;
  const float* __restrict__ X  = pp.X[side];
  const float* __restrict__ W  = pp.W[widx];
  const float* __restrict__ Bv = pp.B[widx];
  const int m0 = blockIdx.x * 128;
  const int n0 = blockIdx.y * 128;
  const float scale = (side == 0) ? SCALE : 1.0f;

  float* outp;
  switch (widx) {
    case 0: outp = g_ql; break;
    case 1: outp = g_qr; break;
    case 2: outp = g_q;  break;
    case 3: outp = g_kl; break;
    case 4: outp = g_kr; break;
    default: outp = g_k; break;
  }

  __shared__ unsigned As[128][36];   // [m][k], pad 36 -> conflict-free frag loads
  __shared__ unsigned Bs[32][136];   // [k][n], pad 136 -> conflict-free frag loads

  const int tid = threadIdx.x;
  const int lane = tid & 31;
  const int warp = tid >> 5;
  const int warpM = warp >> 2;       // 0..1 -> rows 64*warpM
  const int warpN = warp & 3;        // 0..3 -> cols 32*warpN
  const int grp = lane >> 2;         // 0..7
  const int tig = lane & 3;          // 0..3

  float acc[4][4][4];
#pragma unroll
  for (int i=0;i<4;i++)
#pragma unroll
    for (int j=0;j<4;j++)
#pragma unroll
      for (int r=0;r<4;r++) acc[i][j][r]=0.f;

  for (int k0 = 0; k0 < DMODEL; k0 += 32) {
    // ---- stage A tile 128x32 (4 float4 per thread), tf32-converted ----
#pragma unroll
    for (int it = 0; it < 4; ++it) {
      int idx = it*256 + tid;
      int row = idx >> 3;
      int c4  = idx & 7;
      float4 v = *(const float4*)(X + (size_t)(m0+row)*DMODEL + k0 + c4*4);
      As[row][c4*4+0] = tf32cvt(v.x);
      As[row][c4*4+1] = tf32cvt(v.y);
      As[row][c4*4+2] = tf32cvt(v.z);
      As[row][c4*4+3] = tf32cvt(v.w);
    }
    // ---- stage B tile 32x128 ----
#pragma unroll
    for (int it = 0; it < 4; ++it) {
      int idx = it*256 + tid;
      int krow = idx >> 5;
      int c4   = idx & 31;
      float4 v = *(const float4*)(W + (size_t)(k0+krow)*DMODEL + n0 + c4*4);
      Bs[krow][c4*4+0] = tf32cvt(v.x);
      Bs[krow][c4*4+1] = tf32cvt(v.y);
      Bs[krow][c4*4+2] = tf32cvt(v.z);
      Bs[krow][c4*4+3] = tf32cvt(v.w);
    }
    __syncthreads();

#pragma unroll
    for (int kk = 0; kk < 4; ++kk) {
      const int k8 = kk*8;
      unsigned afrag[4][4];
#pragma unroll
      for (int mi = 0; mi < 4; ++mi) {
        int r = warpM*64 + mi*16 + grp;
        afrag[mi][0] = As[r  ][k8 + tig];
        afrag[mi][1] = As[r+8][k8 + tig];
        afrag[mi][2] = As[r  ][k8 + tig + 4];
        afrag[mi][3] = As[r+8][k8 + tig + 4];
      }
      unsigned bfrag[4][2];
#pragma unroll
      for (int nj = 0; nj < 4; ++nj) {
        int c = warpN*32 + nj*8 + grp;
        bfrag[nj][0] = Bs[k8 + tig    ][c];
        bfrag[nj][1] = Bs[k8 + tig + 4][c];
      }
#pragma unroll
      for (int mi = 0; mi < 4; ++mi)
#pragma unroll
        for (int nj = 0; nj < 4; ++nj)
          mma_tf32(acc[mi][nj], afrag[mi], bfrag[nj]);
    }
    __syncthreads();
  }

  // ---- epilogue: bias + scale, scatter to [B,H,S,DK] head layout ----
#pragma unroll
  for (int mi = 0; mi < 4; ++mi) {
#pragma unroll
    for (int nj = 0; nj < 4; ++nj) {
      const int row = m0 + warpM*64 + mi*16 + grp;
      const int col = n0 + warpN*32 + nj*8 + tig*2;  // even -> (dk, dk+1) same head
      const int hh = col >> 6;
      const int dk = col & 63;
      const float2 bias = *(const float2*)(Bv + col);
      {
        const int m = row;
        const int bb = m >> 9, s = m & 511;
        float2 v;
        v.x = (acc[mi][nj][0] + bias.x) * scale;
        v.y = (acc[mi][nj][1] + bias.y) * scale;
        *(float2*)&outp[(((size_t)bb*HEADS + hh)*SEQ + s)*DHEAD + dk] = v;
      }
      {
        const int m = row + 8;
        const int bb = m >> 9, s = m & 511;
        float2 v;
        v.x = (acc[mi][nj][2] + bias.x) * scale;
        v.y = (acc[mi][nj][3] + bias.y) * scale;
        *(float2*)&outp[(((size_t)bb*HEADS + hh)*SEQ + s)*DHEAD + dk] = v;
      }
    }
  }
}

// ---------------------------------------------------------------------------
// Warp utilities
// ---------------------------------------------------------------------------
__device__ __forceinline__ float warpMax(float x) {
#pragma unroll
  for (int off=16; off>0; off>>=1) x = fmaxf(x, __shfl_xor_sync(0xffffffffu, x, off));
  return x;
}
__device__ __forceinline__ float warpSum(float x) {
#pragma unroll
  for (int off=16; off>0; off>>=1) x += __shfl_xor_sync(0xffffffffu, x, off);
  return x;
}
__device__ __forceinline__ float prefixIncl(float x, int lane) {
#pragma unroll
  for (int off=1; off<32; off<<=1) {
    float t = __shfl_up_sync(0xffffffffu, x, off);
    if (lane >= off) x += t;
  }
  return x;
}
__device__ __forceinline__ float suffixIncl(float x, int lane) {
#pragma unroll
  for (int off=1; off<32; off<<=1) {
    float t = __shfl_down_sync(0xffffffffu, x, off);
    if (lane + off < 32) x += t;
  }
  return x;
}

// ---------------------------------------------------------------------------
// Fused attention: one block per (b, h, 32-row q-tile); 256 threads, each
// warp owns 4 q-rows for every row-wise phase.
// ---------------------------------------------------------------------------
__global__ __launch_bounds__(256, 1)
void attn_kernel(const float* __restrict__ mask,
                 const float* __restrict__ span,
                 float* __restrict__ out) {
  extern __shared__ float smbuf[];
  float* Qs = smbuf;                  // [3][32][64]
  float* SL = Qs + 3*32*DHEAD;        // [32][512]
  float* SR = SL + 32*SEQ;            // [32][512]
  float* KT = SR + 32*SEQ;            // [128][68]
  float* RM = KT + 128*68;            // [512]

  __shared__ float wsum[8];

  const int tid = threadIdx.x;
  const int lane = tid & 31;
  const int wid = tid >> 5;
  const int q0 = blockIdx.x * 32;
  const int h = blockIdx.y;
  const int b = blockIdx.z;
  const int bh = (b*HEADS + h)*SEQ;

  // ---- load Q rows (3 branches) + row mask ----
#pragma unroll
  for (int it = 0; it < 6; ++it) {
    int idx = it*256 + tid;          // 1536 float4
    int br = idx >> 9;
    int rem = idx & 511;
    int q = rem >> 4;
    int dc = rem & 15;
    const float* src = (br == 0) ? g_ql : ((br == 1) ? g_qr : g_q);
    float4 v = *(const float4*)(src + (size_t)(bh + q0 + q)*DHEAD + dc*4);
    *(float4*)&Qs[(br*32 + q)*DHEAD + dc*4] = v;
  }
  for (int k = tid; k < SEQ; k += 256) {
    float mv = mask[b*SEQ + k];
    RM[k] = (mv == -10000.0f) ? 1e9f : mv;
  }
  __syncthreads();

  // ---- score phase: dest[q][k] = Q(br) . K(tile), via shared K staging ----
  auto scorePhase = [&](const float* __restrict__ Kbuf, float* __restrict__ dest, int br) {
    for (int kt = 0; kt < 4; ++kt) {
      __syncthreads();   // KT safe to overwrite
#pragma unroll
      for (int it = 0; it < 8; ++it) {
        int idx = it*256 + tid;        // 2048 float4
        int kl = idx >> 4;
        int dc = idx & 15;
        float4 v = *(const float4*)(Kbuf + (size_t)(bh + kt*128 + kl)*DHEAD + dc*4);
        *(float4*)&KT[kl*68 + dc*4] = v;
      }
      __syncthreads();
      float acc[4][4];
#pragma unroll
      for (int i=0;i<4;i++)
#pragma unroll
        for (int j=0;j<4;j++) acc[i][j]=0.f;
#pragma unroll 4
      for (int dc = 0; dc < 16; ++dc) {
        float4 qv[4], kv[4];
#pragma unroll
        for (int i=0;i<4;i++)
          qv[i] = *(const float4*)&Qs[(br*32 + wid*4 + i)*DHEAD + dc*4];
#pragma unroll
        for (int j=0;j<4;j++)
          kv[j] = *(const float4*)&KT[(lane + 32*j)*68 + dc*4];
#pragma unroll
        for (int i=0;i<4;i++)
#pragma unroll
          for (int j=0;j<4;j++) {
            acc[i][j] = fmaf(qv[i].x, kv[j].x, acc[i][j]);
            acc[i][j] = fmaf(qv[i].y, kv[j].y, acc[i][j]);
            acc[i][j] = fmaf(qv[i].z, kv[j].z, acc[i][j]);
            acc[i][j] = fmaf(qv[i].w, kv[j].w, acc[i][j]);
          }
      }
#pragma unroll
      for (int i=0;i<4;i++)
#pragma unroll
        for (int j=0;j<4;j++)
          dest[(wid*4+i)*SEQ + kt*128 + lane + 32*j] = acc[i][j];
    }
  };

  // ================= branch L: theta_l -> inclusive prefix cumsum =========
  scorePhase(g_kl, SL, 0);
  for (int r = 0; r < 4; ++r) {
    const int q = wid*4 + r;
    const int qg = q0 + q;
    float v[16];
    float mx = -1e30f;
#pragma unroll
    for (int jj=0;jj<16;jj++) {
      int k = lane + 32*jj;
      float x = SL[q*SEQ + k];
      v[jj] = (k <= qg) ? x : -1e30f;     // valid: k <= q
      mx = fmaxf(mx, v[jj]);
    }
    mx = warpMax(mx);
    float ssum = 0.f;
#pragma unroll
    for (int jj=0;jj<16;jj++) {
      int k = lane + 32*jj;
      v[jj] = (k <= qg) ? __expf(v[jj]-mx) : 0.f;
      ssum += v[jj];
    }
    ssum = warpSum(ssum);
    float inv = 1.0f/ssum;
    float carry = 0.f;
#pragma unroll
    for (int jj=0;jj<16;jj++) {
      float sc = prefixIncl(v[jj]*inv, lane) + carry;
      SL[q*SEQ + lane + 32*jj] = sc;
      carry = __shfl_sync(0xffffffffu, sc, 31);
    }
  }

  // ===== branch R: theta_r -> inclusive suffix cumsum; SL *= SR ===========
  scorePhase(g_kr, SR, 1);
  for (int r = 0; r < 4; ++r) {
    const int q = wid*4 + r;
    const int qg = q0 + q;
    float v[16];
    float mx = -1e30f;
#pragma unroll
    for (int jj=0;jj<16;jj++) {
      int k = lane + 32*jj;
      float x = SR[q*SEQ + k];
      v[jj] = (k >= qg) ? x : -1e30f;     // valid: k >= q
      mx = fmaxf(mx, v[jj]);
    }
    mx = warpMax(mx);
    float ssum = 0.f;
#pragma unroll
    for (int jj=0;jj<16;jj++) {
      int k = lane + 32*jj;
      v[jj] = (k >= qg) ? __expf(v[jj]-mx) : 0.f;
      ssum += v[jj];
    }
    ssum = warpSum(ssum);
    float inv = 1.0f/ssum;
    float carry = 0.f;
#pragma unroll
    for (int jj=15;jj>=0;jj--) {
      float sc = suffixIncl(v[jj]*inv, lane) + carry;
      int k = lane + 32*jj;
      SL[q*SEQ + k] *= sc;                // SL now holds soft_Mask
      carry = __shfl_sync(0xffffffffu, sc, 0);
    }
  }

  // ===== main branch: p = softmax((scores - rm_q - rm_k) * soft_Mask) =====
  scorePhase(g_k, SR, 2);
  float bce_acc = 0.f;
  for (int r = 0; r < 4; ++r) {
    const int q = wid*4 + r;
    const int qg = q0 + q;
    const float rmq = RM[qg];
    float v[16];
    float mx = -1e30f;
#pragma unroll
    for (int jj=0;jj<16;jj++) {
      int k = lane + 32*jj;
      float raw = SR[q*SEQ + k];
      float m = SL[q*SEQ + k];
      float val = (raw - rmq - RM[k]) * m;
      v[jj] = val;
      mx = fmaxf(mx, val);
    }
    mx = warpMax(mx);
    float ssum = 0.f;
#pragma unroll
    for (int jj=0;jj<16;jj++) {
      v[jj] = __expf(v[jj]-mx);
      ssum += v[jj];
    }
    ssum = warpSum(ssum);
    float inv = 1.0f/ssum;
    const size_t orow = ((size_t)(b*HEADS + h)*SEQ + qg)*SEQ;
    const size_t srow = ((size_t)(h*BATCH + b)*SEQ + qg)*SEQ;
#pragma unroll
    for (int jj=0;jj<16;jj++) {
      int k = lane + 32*jj;
      float p = v[jj]*inv;
      out[orow + k] = p;
      float sp = span[srow + k];
      // BCE identity: -(s*log(sig(p)) + (1-s)*log1p(-sig(p))) = log1p(exp(p)) - s*p
      bce_acc += log1pf(__expf(p)) - sp*p;
    }
  }

  // ---- block reduce BCE partial -> g_partial ----
  bce_acc = warpSum(bce_acc);
  if (lane == 0) wsum[wid] = bce_acc;
  __syncthreads();
  if (tid == 0) {
    double s = 0.0;
#pragma unroll
    for (int w=0;w<8;w++) s += (double)wsum[w];
    g_partial[(blockIdx.z*HEADS + blockIdx.y)*16 + blockIdx.x] = s;
  }
}

// ---------------------------------------------------------------------------
// Final loss reduction
// ---------------------------------------------------------------------------
__global__ void loss_reduce(float* __restrict__ out, int out_size) {
  __shared__ double red[256];
  int tid = threadIdx.x;
  double s = 0.0;
  for (int i = tid; i < NBLK_ATTN; i += 256) s += g_partial[i];
  red[tid] = s;
  __syncthreads();
  for (int off = 128; off > 0; off >>= 1) {
    if (tid < off) red[tid] += red[tid + off];
    __syncthreads();
  }
  if (tid == 0) out[out_size - 1] = (float)(red[0] / (double)P_ELEMS);
}

// ---------------------------------------------------------------------------
extern "C" void kernel_launch(void* const* d_in, const int* in_sizes, int n_in,
                              void* d_out, int out_size) {
  const float* query = (const float*)d_in[0];
  const float* key_t = (const float*)d_in[1];
  const float* mask  = (const float*)d_in[2];
  const float* span  = (const float*)d_in[3];

  ProjParams pp;
  pp.X[0] = query; pp.X[1] = key_t;
  // weight order: [ql, qr, q, kl, kr, k]
  pp.W[0] = (const float*)d_in[4];  pp.B[0] = (const float*)d_in[5];   // Wql
  pp.W[1] = (const float*)d_in[8];  pp.B[1] = (const float*)d_in[9];   // Wqr
  pp.W[2] = (const float*)d_in[12]; pp.B[2] = (const float*)d_in[13];  // Wq
  pp.W[3] = (const float*)d_in[6];  pp.B[3] = (const float*)d_in[7];   // Wkl
  pp.W[4] = (const float*)d_in[10]; pp.B[4] = (const float*)d_in[11];  // Wkr
  pp.W[5] = (const float*)d_in[14]; pp.B[5] = (const float*)d_in[15];  // Wk

  float* out = (float*)d_out;

  dim3 pgrid(32, 6, 6);
  proj_tc<<<pgrid, 256>>>(pp);

  const size_t smem = (size_t)(3*32*DHEAD + 32*SEQ + 32*SEQ + 128*68 + SEQ) * sizeof(float);
  static int attr_set = 0;
  if (!attr_set) {
    cudaFuncSetAttribute(attn_kernel, cudaFuncAttributeMaxDynamicSharedMemorySize, (int)smem);
    attr_set = 1;
  }
  dim3 agrid(SEQ/32, HEADS, BATCH);
  attn_kernel<<<agrid, 256, smem>>>(mask, span, out);

  loss_reduce<<<1, 256>>>(out, out_size);
}

// round 5
// speedup vs baseline: 2.6819x; 1.2313x over previous
#include <cuda_runtime.h>
#include <math.h>

#define BATCH 8
#define HEADS 12
#define SEQ   512
#define DMODEL 768
#define DHEAD 64
#define SCALE 0.03608439182435161f   /* 1/sqrt(768) */

#define PROJ_ELEMS (BATCH*HEADS*SEQ*DHEAD)
#define NBLK_ATTN (16*HEADS*BATCH)
#define P_ELEMS ((size_t)BATCH*HEADS*SEQ*SEQ)
#define XN (BATCH*SEQ*DMODEL)
#define WN (DMODEL*DMODEL)

__device__ float g_ql[PROJ_ELEMS];
__device__ float g_qr[PROJ_ELEMS];
__device__ float g_q [PROJ_ELEMS];
__device__ float g_kl[PROJ_ELEMS];
__device__ float g_kr[PROJ_ELEMS];
__device__ float g_k [PROJ_ELEMS];
__device__ double g_partial[NBLK_ATTN];

// rna-tf32 pre-rounded copies of inputs/weights
__device__ float g_xq[XN];
__device__ float g_xk[XN];
__device__ float g_w6[6][WN];

struct ProjParams {
  const float* B[6];
};
struct PreSrc {
  const float* p[8];
  int len4[8];   // length in float4 units
};

__device__ __forceinline__ unsigned tf32rna(float f) {
  unsigned u;
  asm("cvt.rna.tf32.f32 %0, %1;" : "=r"(u) : "f"(f));
  return u;
}
__device__ __forceinline__ void split_tf32(float x, unsigned& hi, unsigned& lo) {
  unsigned h = tf32rna(x);
  float r = x - __uint_as_float(h);
  hi = h;
  lo = tf32rna(r);
}
__device__ __forceinline__ void mma_tf32(float* c, const unsigned* a, const unsigned* b) {
  asm volatile(
    "mma.sync.aligned.m16n8k8.row.col.f32.tf32.tf32.f32 "
    "{%0,%1,%2,%3},{%4,%5,%6,%7},{%8,%9},{%0,%1,%2,%3};"
    : "+f"(c[0]), "+f"(c[1]), "+f"(c[2]), "+f"(c[3])
    : "r"(a[0]), "r"(a[1]), "r"(a[2]), "r"(a[3]), "r"(b[0]), "r"(b[1]));
}
__device__ __forceinline__ void cpasync16(unsigned dst, const void* src) {
  asm volatile("cp.async.cg.shared.global [%0], [%1], 16;" :: "r"(dst), "l"(src));
}
__device__ __forceinline__ void cpcommit() {
  asm volatile("cp.async.commit_group;");
}

// ---------------------------------------------------------------------------
// Prepass: rna-round inputs and weights into scratch (vectorized).
// grid (512, 8), block 256; seg 0=query, 1=key, 2..7 = weights.
// ---------------------------------------------------------------------------
__global__ void prepass(PreSrc ps) {
  const int seg = blockIdx.y;
  float* dst;
  switch (seg) {
    case 0: dst = g_xq; break;
    case 1: dst = g_xk; break;
    default: dst = g_w6[seg-2]; break;
  }
  const float4* src = (const float4*)ps.p[seg];
  float4* d4 = (float4*)dst;
  const int n4 = ps.len4[seg];
  for (int i = blockIdx.x*blockDim.x + threadIdx.x; i < n4; i += gridDim.x*blockDim.x) {
    float4 v = src[i];
    v.x = __uint_as_float(tf32rna(v.x));
    v.y = __uint_as_float(tf32rna(v.y));
    v.z = __uint_as_float(tf32rna(v.z));
    v.w = __uint_as_float(tf32rna(v.w));
    d4[i] = v;
  }
}

// ---------------------------------------------------------------------------
// Projection GEMM on tensor cores (tf32; data pre-rounded -> exact rna).
// Block tile 128x128, BK=32, 256 threads, warp tile 64x32 (m16n8k8).
// 2-stage cp.async pipeline. grid = (32, 6, 6); z = weight index.
// ---------------------------------------------------------------------------
#define PA_STRIDE 36
#define PB_STRIDE 136
#define PSTAGE_WORDS (128*PA_STRIDE + 32*PB_STRIDE)

__global__ __launch_bounds__(256)
void proj_tc(ProjParams pp) {
  extern __shared__ float psm[];
  const int widx = blockIdx.z;
  const int side = widx / 3;
  const float* __restrict__ X  = side ? g_xk : g_xq;
  const float* __restrict__ W  = g_w6[widx];
  const float* __restrict__ Bv = pp.B[widx];
  const int m0 = blockIdx.x * 128;
  const int n0 = blockIdx.y * 128;
  const float scale = (side == 0) ? SCALE : 1.0f;

  float* outp;
  switch (widx) {
    case 0: outp = g_ql; break;
    case 1: outp = g_qr; break;
    case 2: outp = g_q;  break;
    case 3: outp = g_kl; break;
    case 4: outp = g_kr; break;
    default: outp = g_k; break;
  }

  const int tid = threadIdx.x;
  const int lane = tid & 31;
  const int warp = tid >> 5;
  const int warpM = warp >> 2;
  const int warpN = warp & 3;
  const int grp = lane >> 2;
  const int tig = lane & 3;

  const unsigned smem_base = (unsigned)__cvta_generic_to_shared(psm);

  auto issue_stage = [&](int s, int kt) {
    const unsigned abase = smem_base + s*PSTAGE_WORDS*4;
    const unsigned bbase = abase + 128*PA_STRIDE*4;
    const int k0 = kt*32;
#pragma unroll
    for (int it = 0; it < 4; ++it) {
      int idx = it*256 + tid;
      int row = idx >> 3;
      int c4  = idx & 7;
      cpasync16(abase + (row*PA_STRIDE + c4*4)*4,
                X + (size_t)(m0+row)*DMODEL + k0 + c4*4);
    }
#pragma unroll
    for (int it = 0; it < 4; ++it) {
      int idx = it*256 + tid;
      int krow = idx >> 5;
      int c4   = idx & 31;
      cpasync16(bbase + (krow*PB_STRIDE + c4*4)*4,
                W + (size_t)(k0+krow)*DMODEL + n0 + c4*4);
    }
    cpcommit();
  };

  float acc[4][4][4];
#pragma unroll
  for (int i=0;i<4;i++)
#pragma unroll
    for (int j=0;j<4;j++)
#pragma unroll
      for (int r=0;r<4;r++) acc[i][j][r]=0.f;

  issue_stage(0, 0);

  const int NK = DMODEL/32;   // 24
  for (int kt = 0; kt < NK; ++kt) {
    const int cur = kt & 1;
    if (kt + 1 < NK) {
      issue_stage(cur ^ 1, kt + 1);
      asm volatile("cp.async.wait_group 1;");
    } else {
      asm volatile("cp.async.wait_group 0;");
    }
    __syncthreads();

    const unsigned* As = (const unsigned*)(psm + cur*PSTAGE_WORDS);
    const unsigned* Bs = As + 128*PA_STRIDE;

#pragma unroll
    for (int kk = 0; kk < 4; ++kk) {
      const int k8 = kk*8;
      unsigned afrag[4][4];
#pragma unroll
      for (int mi = 0; mi < 4; ++mi) {
        int r = warpM*64 + mi*16 + grp;
        afrag[mi][0] = As[r*PA_STRIDE + k8 + tig];
        afrag[mi][1] = As[(r+8)*PA_STRIDE + k8 + tig];
        afrag[mi][2] = As[r*PA_STRIDE + k8 + tig + 4];
        afrag[mi][3] = As[(r+8)*PA_STRIDE + k8 + tig + 4];
      }
      unsigned bfrag[4][2];
#pragma unroll
      for (int nj = 0; nj < 4; ++nj) {
        int c = warpN*32 + nj*8 + grp;
        bfrag[nj][0] = Bs[(k8 + tig)*PB_STRIDE + c];
        bfrag[nj][1] = Bs[(k8 + tig + 4)*PB_STRIDE + c];
      }
#pragma unroll
      for (int mi = 0; mi < 4; ++mi)
#pragma unroll
        for (int nj = 0; nj < 4; ++nj)
          mma_tf32(acc[mi][nj], afrag[mi], bfrag[nj]);
    }
    __syncthreads();
  }

  // ---- epilogue: bias + scale, scatter to [B,H,S,DK] head layout ----
#pragma unroll
  for (int mi = 0; mi < 4; ++mi) {
#pragma unroll
    for (int nj = 0; nj < 4; ++nj) {
      const int row = m0 + warpM*64 + mi*16 + grp;
      const int col = n0 + warpN*32 + nj*8 + tig*2;
      const int hh = col >> 6;
      const int dk = col & 63;
      const float2 bias = *(const float2*)(Bv + col);
      {
        const int m = row;
        const int bb = m >> 9, s = m & 511;
        float2 v;
        v.x = (acc[mi][nj][0] + bias.x) * scale;
        v.y = (acc[mi][nj][1] + bias.y) * scale;
        *(float2*)&outp[(((size_t)bb*HEADS + hh)*SEQ + s)*DHEAD + dk] = v;
      }
      {
        const int m = row + 8;
        const int bb = m >> 9, s = m & 511;
        float2 v;
        v.x = (acc[mi][nj][2] + bias.x) * scale;
        v.y = (acc[mi][nj][3] + bias.y) * scale;
        *(float2*)&outp[(((size_t)bb*HEADS + hh)*SEQ + s)*DHEAD + dk] = v;
      }
    }
  }
}

// ---------------------------------------------------------------------------
// Warp utilities
// ---------------------------------------------------------------------------
__device__ __forceinline__ float warpMax(float x) {
#pragma unroll
  for (int off=16; off>0; off>>=1) x = fmaxf(x, __shfl_xor_sync(0xffffffffu, x, off));
  return x;
}
__device__ __forceinline__ float warpSum(float x) {
#pragma unroll
  for (int off=16; off>0; off>>=1) x += __shfl_xor_sync(0xffffffffu, x, off);
  return x;
}
__device__ __forceinline__ float prefixIncl(float x, int lane) {
#pragma unroll
  for (int off=1; off<32; off<<=1) {
    float t = __shfl_up_sync(0xffffffffu, x, off);
    if (lane >= off) x += t;
  }
  return x;
}
__device__ __forceinline__ float suffixIncl(float x, int lane) {
#pragma unroll
  for (int off=1; off<32; off<<=1) {
    float t = __shfl_down_sync(0xffffffffu, x, off);
    if (lane + off < 32) x += t;
  }
  return x;
}

// ---------------------------------------------------------------------------
// Fused attention: one block per (b, h, 32-row q-tile); 256 threads.
// Score GEMMs use 3xTF32 split MMA (fp32-equivalent accuracy).
// ---------------------------------------------------------------------------
#define QS_STRIDE 68
#define KT_STRIDE 68

__global__ __launch_bounds__(256, 1)
void attn_kernel(const float* __restrict__ mask,
                 const float* __restrict__ span,
                 float* __restrict__ out) {
  extern __shared__ float smbuf[];
  float* Qs = smbuf;                     // [3][32][68] raw fp32
  float* SL = Qs + 3*32*QS_STRIDE;       // [32][512]
  float* SR = SL + 32*SEQ;               // [32][512]
  float* KT = SR + 32*SEQ;               // [128][68] raw fp32
  float* RM = KT + 128*KT_STRIDE;        // [512]

  __shared__ float wsum[8];

  const int tid = threadIdx.x;
  const int lane = tid & 31;
  const int wid = tid >> 5;
  const int grp = lane >> 2;
  const int tig = lane & 3;
  const int q0 = blockIdx.x * 32;
  const int h = blockIdx.y;
  const int b = blockIdx.z;
  const int bh = (b*HEADS + h)*SEQ;

  // ---- load Q rows (3 branches) + row mask ----
#pragma unroll
  for (int it = 0; it < 6; ++it) {
    int idx = it*256 + tid;          // 1536 float4
    int br = idx >> 9;
    int rem = idx & 511;
    int q = rem >> 4;
    int dc = rem & 15;
    const float* src = (br == 0) ? g_ql : ((br == 1) ? g_qr : g_q);
    float4 v = *(const float4*)(src + (size_t)(bh + q0 + q)*DHEAD + dc*4);
    *(float4*)&Qs[(br*32 + q)*QS_STRIDE + dc*4] = v;
  }
  for (int k = tid; k < SEQ; k += 256) {
    float mv = mask[b*SEQ + k];
    RM[k] = (mv == -10000.0f) ? 1e9f : mv;
  }
  __syncthreads();

  // ---- score phase on tensor cores (3xTF32): dest[q][k] = Q(br) . K ----
  auto scorePhase = [&](const float* __restrict__ Kbuf, float* __restrict__ dest, int br) {
    for (int kt = 0; kt < 4; ++kt) {
      __syncthreads();   // KT safe to overwrite
#pragma unroll
      for (int it = 0; it < 8; ++it) {
        int idx = it*256 + tid;        // 2048 float4 = 128 rows x 16 chunks
        int kl = idx >> 4;
        int dc = idx & 15;
        float4 v = *(const float4*)(Kbuf + (size_t)(bh + kt*128 + kl)*DHEAD + dc*4);
        *(float4*)&KT[kl*KT_STRIDE + dc*4] = v;
      }
      __syncthreads();

      float acc[2][2][4];
#pragma unroll
      for (int i=0;i<2;i++)
#pragma unroll
        for (int j=0;j<2;j++)
#pragma unroll
          for (int r=0;r<4;r++) acc[i][j][r]=0.f;

#pragma unroll
      for (int kk = 0; kk < 8; ++kk) {
        const int k8 = kk*8;
        unsigned ahi[2][4], alo[2][4];
#pragma unroll
        for (int mi = 0; mi < 2; ++mi) {
          int r = br*32 + mi*16 + grp;
          split_tf32(Qs[r*QS_STRIDE + k8 + tig],       ahi[mi][0], alo[mi][0]);
          split_tf32(Qs[(r+8)*QS_STRIDE + k8 + tig],   ahi[mi][1], alo[mi][1]);
          split_tf32(Qs[r*QS_STRIDE + k8 + tig + 4],   ahi[mi][2], alo[mi][2]);
          split_tf32(Qs[(r+8)*QS_STRIDE + k8 + tig+4], ahi[mi][3], alo[mi][3]);
        }
        unsigned bhi[2][2], blo[2][2];
#pragma unroll
        for (int nj = 0; nj < 2; ++nj) {
          int n = wid*16 + nj*8 + grp;
          split_tf32(KT[n*KT_STRIDE + k8 + tig],     bhi[nj][0], blo[nj][0]);
          split_tf32(KT[n*KT_STRIDE + k8 + tig + 4], bhi[nj][1], blo[nj][1]);
        }
#pragma unroll
        for (int mi = 0; mi < 2; ++mi)
#pragma unroll
          for (int nj = 0; nj < 2; ++nj) {
            mma_tf32(acc[mi][nj], ahi[mi], blo[nj]);
            mma_tf32(acc[mi][nj], alo[mi], bhi[nj]);
            mma_tf32(acc[mi][nj], ahi[mi], bhi[nj]);
          }
      }

      // write 32x16 slice
#pragma unroll
      for (int mi = 0; mi < 2; ++mi)
#pragma unroll
        for (int nj = 0; nj < 2; ++nj) {
          const int row = mi*16 + grp;
          const int col = kt*128 + wid*16 + nj*8 + tig*2;
          *(float2*)&dest[row*SEQ + col]     = make_float2(acc[mi][nj][0], acc[mi][nj][1]);
          *(float2*)&dest[(row+8)*SEQ + col] = make_float2(acc[mi][nj][2], acc[mi][nj][3]);
        }
    }
    __syncthreads();   // scores visible to row-owning warps
  };

  // ================= branch L: theta_l -> inclusive prefix cumsum =========
  scorePhase(g_kl, SL, 0);
  for (int r = 0; r < 4; ++r) {
    const int q = wid*4 + r;
    const int qg = q0 + q;
    float v[16];
    float mx = -1e30f;
#pragma unroll
    for (int jj=0;jj<16;jj++) {
      int k = lane + 32*jj;
      float x = SL[q*SEQ + k];
      v[jj] = (k <= qg) ? x : -1e30f;     // valid: k <= q
      mx = fmaxf(mx, v[jj]);
    }
    mx = warpMax(mx);
    float ssum = 0.f;
#pragma unroll
    for (int jj=0;jj<16;jj++) {
      int k = lane + 32*jj;
      v[jj] = (k <= qg) ? __expf(v[jj]-mx) : 0.f;
      ssum += v[jj];
    }
    ssum = warpSum(ssum);
    float inv = 1.0f/ssum;
    float carry = 0.f;
#pragma unroll
    for (int jj=0;jj<16;jj++) {
      float sc = prefixIncl(v[jj]*inv, lane) + carry;
      SL[q*SEQ + lane + 32*jj] = sc;
      carry = __shfl_sync(0xffffffffu, sc, 31);
    }
  }
  __syncthreads();

  // ===== branch R: theta_r -> inclusive suffix cumsum; SL *= SR ===========
  scorePhase(g_kr, SR, 1);
  for (int r = 0; r < 4; ++r) {
    const int q = wid*4 + r;
    const int qg = q0 + q;
    float v[16];
    float mx = -1e30f;
#pragma unroll
    for (int jj=0;jj<16;jj++) {
      int k = lane + 32*jj;
      float x = SR[q*SEQ + k];
      v[jj] = (k >= qg) ? x : -1e30f;     // valid: k >= q
      mx = fmaxf(mx, v[jj]);
    }
    mx = warpMax(mx);
    float ssum = 0.f;
#pragma unroll
    for (int jj=0;jj<16;jj++) {
      int k = lane + 32*jj;
      v[jj] = (k >= qg) ? __expf(v[jj]-mx) : 0.f;
      ssum += v[jj];
    }
    ssum = warpSum(ssum);
    float inv = 1.0f/ssum;
    float carry = 0.f;
#pragma unroll
    for (int jj=15;jj>=0;jj--) {
      float sc = suffixIncl(v[jj]*inv, lane) + carry;
      int k = lane + 32*jj;
      SL[q*SEQ + k] *= sc;                // SL now holds soft_Mask
      carry = __shfl_sync(0xffffffffu, sc, 0);
    }
  }
  __syncthreads();

  // ===== main branch: p = softmax((scores - rm_q - rm_k) * soft_Mask) =====
  scorePhase(g_k, SR, 2);
  float bce_acc = 0.f;
  for (int r = 0; r < 4; ++r) {
    const int q = wid*4 + r;
    const int qg = q0 + q;
    const float rmq = RM[qg];
    float v[16];
    float mx = -1e30f;
#pragma unroll
    for (int jj=0;jj<16;jj++) {
      int k = lane + 32*jj;
      float raw = SR[q*SEQ + k];
      float m = SL[q*SEQ + k];
      float val = (raw - rmq - RM[k]) * m;
      v[jj] = val;
      mx = fmaxf(mx, val);
    }
    mx = warpMax(mx);
    float ssum = 0.f;
#pragma unroll
    for (int jj=0;jj<16;jj++) {
      v[jj] = __expf(v[jj]-mx);
      ssum += v[jj];
    }
    ssum = warpSum(ssum);
    float inv = 1.0f/ssum;
    const size_t orow = ((size_t)(b*HEADS + h)*SEQ + qg)*SEQ;
    const size_t srow = ((size_t)(h*BATCH + b)*SEQ + qg)*SEQ;
#pragma unroll
    for (int jj=0;jj<16;jj++) {
      int k = lane + 32*jj;
      float p = v[jj]*inv;
      out[orow + k] = p;
      float sp = span[srow + k];
      // BCE identity: -(s*log(sig(p)) + (1-s)*log1p(-sig(p))) = log1p(exp(p)) - s*p
      bce_acc += log1pf(__expf(p)) - sp*p;
    }
  }

  // ---- block reduce BCE partial -> g_partial ----
  bce_acc = warpSum(bce_acc);
  if (lane == 0) wsum[wid] = bce_acc;
  __syncthreads();
  if (tid == 0) {
    double s = 0.0;
#pragma unroll
    for (int w=0;w<8;w++) s += (double)wsum[w];
    g_partial[(blockIdx.z*HEADS + blockIdx.y)*16 + blockIdx.x] = s;
  }
}

// ---------------------------------------------------------------------------
// Final loss reduction
// ---------------------------------------------------------------------------
__global__ void loss_reduce(float* __restrict__ out, int out_size) {
  __shared__ double red[256];
  int tid = threadIdx.x;
  double s = 0.0;
  for (int i = tid; i < NBLK_ATTN; i += 256) s += g_partial[i];
  red[tid] = s;
  __syncthreads();
  for (int off = 128; off > 0; off >>= 1) {
    if (tid < off) red[tid] += red[tid + off];
    __syncthreads();
  }
  if (tid == 0) out[out_size - 1] = (float)(red[0] / (double)P_ELEMS);
}

// ---------------------------------------------------------------------------
extern "C" void kernel_launch(void* const* d_in, const int* in_sizes, int n_in,
                              void* d_out, int out_size) {
  const float* query = (const float*)d_in[0];
  const float* key_t = (const float*)d_in[1];
  const float* mask  = (const float*)d_in[2];
  const float* span  = (const float*)d_in[3];

  PreSrc ps;
  ps.p[0] = query;                  ps.len4[0] = XN/4;
  ps.p[1] = key_t;                  ps.len4[1] = XN/4;
  // weight order (scratch index): [ql, qr, q, kl, kr, k]
  ps.p[2] = (const float*)d_in[4];  ps.len4[2] = WN/4;  // Wql
  ps.p[3] = (const float*)d_in[8];  ps.len4[3] = WN/4;  // Wqr
  ps.p[4] = (const float*)d_in[12]; ps.len4[4] = WN/4;  // Wq
  ps.p[5] = (const float*)d_in[6];  ps.len4[5] = WN/4;  // Wkl
  ps.p[6] = (const float*)d_in[10]; ps.len4[6] = WN/4;  // Wkr
  ps.p[7] = (const float*)d_in[14]; ps.len4[7] = WN/4;  // Wk

  ProjParams pp;
  pp.B[0] = (const float*)d_in[5];   // bql
  pp.B[1] = (const float*)d_in[9];   // bqr
  pp.B[2] = (const float*)d_in[13];  // bq
  pp.B[3] = (const float*)d_in[7];   // bkl
  pp.B[4] = (const float*)d_in[11];  // bkr
  pp.B[5] = (const float*)d_in[15];  // bk

  float* out = (float*)d_out;

  const size_t psmem = (size_t)(2*PSTAGE_WORDS) * sizeof(float);
  const size_t asmem = (size_t)(3*32*QS_STRIDE + 32*SEQ + 32*SEQ + 128*KT_STRIDE + SEQ) * sizeof(float);
  static int attr_set = 0;
  if (!attr_set) {
    cudaFuncSetAttribute(proj_tc, cudaFuncAttributeMaxDynamicSharedMemorySize, (int)psmem);
    cudaFuncSetAttribute(attn_kernel, cudaFuncAttributeMaxDynamicSharedMemorySize, (int)asmem);
    attr_set = 1;
  }

  prepass<<<dim3(512, 8), 256>>>(ps);

  dim3 pgrid(32, 6, 6);
  proj_tc<<<pgrid, 256, psmem>>>(pp);

  dim3 agrid(SEQ/32, HEADS, BATCH);
  attn_kernel<<<agrid, 256, asmem>>>(mask, span, out);

  loss_reduce<<<1, 256>>>(out, out_size);
}